// round 16
// baseline (speedup 1.0000x reference)
#include <cuda_runtime.h>

// LoCon1d: out[b][o][s] = sum_{c,k} in[b][c][s+k-1] * w[o][c][s][k] + bias[o][s]
// B=16, Cin=64, Cout=64, S=1024, K=3 (zero pad)
//
//  1) transpose_kernel: input (B,C,S) -> g_trans[c][1+s][b], zero halo rows
//  2) locon1d_kernel:   R15 layout (S_TILE=64, O_TILE=4, 4-way v-broadcast)
//                       at 3 resident blocks/SM (6-stage ring, lb(256,3)).

#define S_LEN   1024
#define CIN     64
#define COUT    64
#define BATCH   16
#define KW      3
#define S_TILE  64
#define O_TILE  4
#define THREADS 256

// transposed input: [c][j=0..1025][b=0..15], j = s+1 (rows 0 and 1025 zero)
#define TR_J    (S_LEN + 2)
__device__ float g_trans[CIN * TR_J * BATCH];

// ring stage:
//   weight: 4 o-slices, each 64s*3k f32 = 768B padded to 800B -> 3200B
//   input:  66 rows x 5 f4 (stride-5, 4 used) = 5280B
#define W_OSTRIDE_B  800
#define IN_OFF_B     3200
#define STAGE_BYTES  8576            // 3200 + 5280 = 8480 -> 67*128
#define N_STAGES     6
#define SMEM_BYTES   (N_STAGES * STAGE_BYTES)   // 51456 -> 3 blocks/SM

typedef unsigned long long u64;

__device__ __forceinline__ u64 splat2(float w) {
    u64 r;
    asm("mov.b64 %0, {%1, %1};" : "=l"(r) : "f"(w));
    return r;
}
__device__ __forceinline__ void fma2(u64 &d, u64 a, u64 b) {
    asm("fma.rn.f32x2 %0, %1, %2, %0;" : "+l"(d) : "l"(a), "l"(b));
}
__device__ __forceinline__ float2 u2f(u64 u) {
    float2 r;
    asm("mov.b64 {%0, %1}, %2;" : "=f"(r.x), "=f"(r.y) : "l"(u));
    return r;
}
__device__ __forceinline__ void cp16(unsigned dst, const void* src) {
    asm volatile("cp.async.cg.shared.global [%0], [%1], 16;" :: "r"(dst), "l"(src));
}
__device__ __forceinline__ void cp_commit() {
    asm volatile("cp.async.commit_group;");
}
__device__ __forceinline__ void cp_wait4() {
    asm volatile("cp.async.wait_group 4;");
}

// ---------------------------------------------------------------------------
// transpose: input[b][c][s] -> g_trans[c][1+s][b]; zero rows j=0 and j=1025
// ---------------------------------------------------------------------------
__global__ void __launch_bounds__(256)
transpose_kernel(const float* __restrict__ input)
{
    __shared__ float tile[BATCH][65];

    const int c  = blockIdx.x;
    const int s0 = blockIdx.y * 64;
    const int tid = threadIdx.x;

    #pragma unroll
    for (int r = 0; r < 4; ++r) {
        const int idx = tid + r * 256;
        const int b  = idx >> 6;
        const int sl = idx & 63;
        tile[b][sl] = input[((size_t)b * CIN + c) * S_LEN + s0 + sl];
    }
    __syncthreads();

    #pragma unroll
    for (int r = 0; r < 4; ++r) {
        const int idx = tid + r * 256;
        const int b  = idx & 15;
        const int sl = idx >> 4;
        g_trans[((size_t)c * TR_J + 1 + s0 + sl) * BATCH + b] = tile[b][sl];
    }

    if (blockIdx.x == 0 && blockIdx.y == 0) {
        for (int e = tid; e < CIN * BATCH; e += 256) {
            const int cc = e >> 4, bb = e & 15;
            g_trans[((size_t)cc * TR_J + 0) * BATCH + bb]        = 0.f;
            g_trans[((size_t)cc * TR_J + TR_J - 1) * BATCH + bb] = 0.f;
        }
    }
}

// ---------------------------------------------------------------------------
// main conv: grid (16 s-tiles, 16 o-tiles) = 256 blocks x 256 threads.
// warp w: s_loc = 8w + (lane>>2), o_l = lane&3; thread owns 16 batches.
// ---------------------------------------------------------------------------
__global__ void __launch_bounds__(THREADS, 3)
locon1d_kernel(const float* __restrict__ weight,
               const float* __restrict__ bias,
               float* __restrict__ out)
{
    extern __shared__ char smem[];

    const int s0 = blockIdx.x * S_TILE;
    const int o0 = blockIdx.y * O_TILE;
    const int tid = threadIdx.x;
    const unsigned sh_u = (unsigned)__cvta_generic_to_shared(smem);

    // ---- cp.async fill per stage ------------------------------------------
    // weight: tid<192: o = tid/48, r = tid%48 -> 768B contiguous run per (o,c)
    const int wo = tid / 48, wr = tid % 48;
    const float* wsrc = weight + ((size_t)(o0 + wo) * CIN) * (S_LEN * 3)
                               + (size_t)s0 * 3 + wr * 4;
    const unsigned wdst_off = (unsigned)(wo * W_OSTRIDE_B + wr * 16);
    // input: f2 t in [0,264): j = t>>2, bq = t&3 -> f4 slot 5j+bq
    const int ijA = tid >> 2,          ibA = tid & 3;          // t = tid (all)
    const int ijB = (tid + 256) >> 2,  ibB = tid & 3;          // t = tid+256
    const float* isrcA = g_trans + ((size_t)(s0 + ijA)) * BATCH + ibA * 4;
    const float* isrcB = g_trans + ((size_t)(s0 + ijB)) * BATCH + ibB * 4;
    const unsigned idstA = (unsigned)(IN_OFF_B + (5 * ijA + ibA) * 16);
    const unsigned idstB = (unsigned)(IN_OFF_B + (5 * ijB + ibB) * 16);

    // slot must be passed explicitly (6 stages, not a power of 2)
    auto WISSUE = [&](int c, int slot) {
        const unsigned stg = sh_u + (unsigned)(slot * STAGE_BYTES);
        if (tid < 192)
            cp16(stg + wdst_off, wsrc + (size_t)c * (S_LEN * 3));
        cp16(stg + idstA, isrcA + (size_t)c * (TR_J * BATCH));
        if (tid < 8)
            cp16(stg + idstB, isrcB + (size_t)c * (TR_J * BATCH));
        cp_commit();
    };

    // prologue: 5 stages. Before iter-c wait: commits = 5+c; wait_group 4 ->
    // completed >= c+1 -> group c (stage c) resident. 4-stage slack.
    WISSUE(0, 0); WISSUE(1, 1); WISSUE(2, 2); WISSUE(3, 3); WISSUE(4, 4);

    // ---- compute mapping --------------------------------------------------
    const int lane = tid & 31;
    const int wrp  = tid >> 5;
    const int o_l  = lane & 3;
    const int sl3  = lane >> 2;          // 0..7
    const int s_loc = wrp * 8 + sl3;     // 0..63
    const int o = o0 + o_l;
    const int s = s0 + s_loc;

    u64 acc[8];
    #pragma unroll
    for (int p = 0; p < 8; ++p) acc[p] = 0ull;

    int rslot = 0;           // slot of stage c      (c % 6)
    int wslot = 5;           // slot of stage c+5    ((c+5) % 6)
    for (int c = 0; c < CIN; ++c) {
        cp_wait4();
        __syncthreads();     // stage c visible; slot (c-1)%6 now free

        // refill first: stage c+5 -> slot (c+5)%6 == (c-1)%6 (just freed;
        // readers use rslot = c%6; in-flight stages c+1..c+4 use other slots)
        if (c + 5 < CIN) WISSUE(c + 5, wslot); else cp_commit();

        const char* stg = smem + rslot * STAGE_BYTES;

        // weights: o-slice stride 200 f32 -> bank (8*o_l + 3*s_loc + k) mod 32,
        // distinct across the warp -> conflict-free scalar LDS
        const float* wfl = reinterpret_cast<const float*>(stg);
        float w[3];
        #pragma unroll
        for (int k = 0; k < KW; ++k)
            w[k] = wfl[o_l * (W_OSTRIDE_B / 4) + s_loc * 3 + k];

        // input rows j = s_loc+k, 4 f4 each; 4-way o_l broadcast -> 128B
        // unique per warp instruction = 1 crossbar cycle
        const ulonglong2* vstg =
            reinterpret_cast<const ulonglong2*>(stg + IN_OFF_B);
        ulonglong2 v[3][4];
        #pragma unroll
        for (int k = 0; k < KW; ++k)
            #pragma unroll
            for (int bq = 0; bq < 4; ++bq)
                v[k][bq] = vstg[5 * (s_loc + k) + bq];

        #pragma unroll
        for (int k = 0; k < KW; ++k) {
            const u64 w2 = splat2(w[k]);
            #pragma unroll
            for (int bq = 0; bq < 4; ++bq) {
                fma2(acc[2 * bq],     v[k][bq].x, w2);
                fma2(acc[2 * bq + 1], v[k][bq].y, w2);
            }
        }

        if (++rslot == N_STAGES) rslot = 0;
        if (++wslot == N_STAGES) wslot = 0;
    }

    // ---- epilogue: bias + store ------------------------------------------
    {
        const float bz = bias[(size_t)o * S_LEN + s];
        #pragma unroll
        for (int p = 0; p < 8; ++p) {
            const float2 a = u2f(acc[p]);
            const int b0 = 2 * p;
            out[((size_t)(b0       * COUT + o)) * S_LEN + s] = a.x + bz;
            out[((size_t)((b0 + 1) * COUT + o)) * S_LEN + s] = a.y + bz;
        }
    }
}

extern "C" void kernel_launch(void* const* d_in, const int* in_sizes, int n_in,
                              void* d_out, int out_size) {
    const float* input  = (const float*)d_in[0];
    const float* weight = (const float*)d_in[1];
    const float* bias   = (const float*)d_in[2];
    float* out = (float*)d_out;

    cudaFuncSetAttribute(locon1d_kernel,
                         cudaFuncAttributeMaxDynamicSharedMemorySize, SMEM_BYTES);

    dim3 tgrid(CIN, S_LEN / 64);                 // (64, 16)
    transpose_kernel<<<tgrid, 256>>>(input);

    dim3 grid(S_LEN / S_TILE, COUT / O_TILE);    // (16, 16) = 256 blocks
    locon1d_kernel<<<grid, THREADS, SMEM_BYTES>>>(weight, bias, out);
}

// round 17
// speedup vs baseline: 1.0275x; 1.0275x over previous
#include <cuda_runtime.h>

// LoCon1d: out[b][o][s] = sum_{c,k} in[b][c][s+k-1] * w[o][c][s][k] + bias[o][s]
// B=16, Cin=64, Cout=64, S=1024, K=3 (zero pad)
//
// R17: (1) prefetch_kernel pulls the 50.3MB weight into L2 at max streaming
//      BW; (2) conv kernel = R3 (best known, minimal DRAM bytes) now serving
//      weight reads from L2.

#define S_LEN   1024
#define CIN     64
#define COUT    64
#define BATCH   16
#define KW      3
#define S_TILE  16
#define O_TILE  16
#define HALO    (S_TILE + 2)     // 18
#define THREADS 128
#define ROW4    5
#define SH4_CNT (CIN * HALO * ROW4)          // 5760 float4
#define SMEM_BYTES (SH4_CNT * 16)            // 92160 B

typedef unsigned long long u64;

__device__ float g_sink[1024];   // never actually written (predicate false)

__device__ __forceinline__ u64 splat2(float w) {
    u64 r;
    asm("mov.b64 %0, {%1, %1};" : "=l"(r) : "f"(w));
    return r;
}
__device__ __forceinline__ void fma2(u64 &d, u64 a, u64 b) {
    asm("fma.rn.f32x2 %0, %1, %2, %0;" : "+l"(d) : "l"(a), "l"(b));
}
__device__ __forceinline__ float2 u2f(u64 u) {
    float2 r;
    asm("mov.b64 {%0, %1}, %2;" : "=f"(r.x), "=f"(r.y) : "l"(u));
    return r;
}

#define WF(warr, i) (((i) & 3) == 0 ? (warr)[(i) >> 2].x : \
                     ((i) & 3) == 1 ? (warr)[(i) >> 2].y : \
                     ((i) & 3) == 2 ? (warr)[(i) >> 2].z : (warr)[(i) >> 2].w)

// ---------------------------------------------------------------------------
// prefetch: stream the whole weight tensor through L2 (__ldcg = cache in L2).
// Grid-stride, unroll-8, no inter-load dependencies -> max MLP.
// ---------------------------------------------------------------------------
__global__ void __launch_bounds__(256)
prefetch_kernel(const float4* __restrict__ w, int n4)
{
    const int stride = gridDim.x * blockDim.x;
    int i = blockIdx.x * blockDim.x + threadIdx.x;

    float4 acc = make_float4(0.f, 0.f, 0.f, 0.f);
    #pragma unroll 8
    for (; i < n4; i += stride) {
        const float4 v = __ldcg(w + i);
        acc.x += v.x; acc.y += v.y; acc.z += v.z; acc.w += v.w;
    }
    // dead-code guard the compiler can't remove; condition is never true for
    // finite random inputs in a deterministic way (and the write is benign).
    if (acc.x + acc.y + acc.z + acc.w == 1.2345678e38f)
        g_sink[(blockIdx.x * 256 + threadIdx.x) & 1023] = acc.x;
}

// ---------------------------------------------------------------------------
// conv: R3 kernel verbatim (27.4us baseline; weights now L2-resident)
// ---------------------------------------------------------------------------
__global__ void __launch_bounds__(THREADS, 2)
locon1d_kernel(const float* __restrict__ input,
               const float* __restrict__ weight,
               const float* __restrict__ bias,
               float* __restrict__ out)
{
    extern __shared__ float4 sh4[];

    const int s0 = blockIdx.x * S_TILE;
    const int o0 = blockIdx.y * O_TILE;
    const int tid = threadIdx.x;

    // ---------------- fill input tile into shared -------------------------
    for (int m = tid; m < CIN * HALO * 4; m += THREADS) {
        const int bq = m & 3;
        const int t  = m >> 2;
        const int j  = t % HALO;
        const int c  = t / HALO;
        const int s  = s0 - 1 + j;
        float4 v = make_float4(0.f, 0.f, 0.f, 0.f);
        if ((unsigned)s < (unsigned)S_LEN) {
            const float* p = input + ((size_t)(4 * bq) * CIN + c) * S_LEN + s;
            v.x = p[0];
            v.y = p[(size_t)CIN * S_LEN];
            v.z = p[2 * (size_t)CIN * S_LEN];
            v.w = p[3 * (size_t)CIN * S_LEN];
        }
        sh4[m + (m >> 2)] = v;
    }
    __syncthreads();

    // ---------------- thread mapping --------------------------------------
    const int o_l = tid >> 4;          // 0..7
    const int sg  = (tid >> 2) & 3;    // 0..3  (4 s each)
    const int bg  = tid & 3;           // 0..3  (4 b each)
    const int oA = o0 + o_l;
    const int oB = o0 + o_l + 8;
    const int sbase = s0 + sg * 4;
    const int jbase = sg * 4;

    const ulonglong2* shp2 = reinterpret_cast<const ulonglong2*>(sh4);
    const int svb = ROW4 * jbase + bg;

    const float4* wpA = reinterpret_cast<const float4*>(weight) +
                        (((size_t)oA * CIN) * S_LEN * 3 + (size_t)sbase * 3) / 4;
    const float4* wpB = reinterpret_cast<const float4*>(weight) +
                        (((size_t)oB * CIN) * S_LEN * 3 + (size_t)sbase * 3) / 4;

    u64 acc[2][4][2];
    #pragma unroll
    for (int i = 0; i < 2; ++i)
        #pragma unroll
        for (int j = 0; j < 4; ++j) { acc[i][j][0] = 0ull; acc[i][j][1] = 0ull; }

    float4 wa[4][3], wb[4][3];     // 4-deep weight prefetch ring
    ulonglong2 v[2][6];            // 2-deep input prefetch

    auto WLOAD = [&](int c) {
        const float4* pa = wpA + (size_t)c * 768;
        const float4* pb = wpB + (size_t)c * 768;
        #pragma unroll
        for (int i = 0; i < 3; ++i) {
            wa[c & 3][i] = __ldcs(pa + i);
            wb[c & 3][i] = __ldcs(pb + i);
        }
    };
    auto VLOAD = [&](int c) {
        const int base = 90 * c + svb;
        #pragma unroll
        for (int d = 0; d < 6; ++d)
            v[c & 1][d] = shp2[base + ROW4 * d];
    };

    WLOAD(0); WLOAD(1); WLOAD(2); WLOAD(3);
    VLOAD(0);

    #pragma unroll 4
    for (int c = 0; c < CIN; ++c) {
        if (c + 1 < CIN) VLOAD(c + 1);      // writes v[(c+1)&1] — safe
        const int cb = c & 1;
        const int wq = c & 3;
        #pragma unroll
        for (int ss = 0; ss < 4; ++ss) {
            #pragma unroll
            for (int k = 0; k < KW; ++k) {
                const int d  = ss + k;
                const int wi = ss * 3 + k;
                const u64 lo = v[cb][d].x;
                const u64 hi = v[cb][d].y;
                const u64 sa = splat2(WF(wa[wq], wi));
                fma2(acc[0][ss][0], lo, sa);
                fma2(acc[0][ss][1], hi, sa);
                const u64 sb = splat2(WF(wb[wq], wi));
                fma2(acc[1][ss][0], lo, sb);
                fma2(acc[1][ss][1], hi, sb);
            }
        }
        // prefetch AFTER compute (register dep prevents the R2 clobber)
        if (c + 4 < CIN) WLOAD(c + 4);
    }

    // ---------------- epilogue: bias + store -------------------------------
    #pragma unroll
    for (int o2 = 0; o2 < 2; ++o2) {
        const int o = o2 ? oB : oA;
        const float4 bz = *reinterpret_cast<const float4*>(bias + (size_t)o * S_LEN + sbase);
        #pragma unroll
        for (int pr = 0; pr < 2; ++pr) {
            const float2 f0 = u2f(acc[o2][0][pr]);
            const float2 f1 = u2f(acc[o2][1][pr]);
            const float2 f2 = u2f(acc[o2][2][pr]);
            const float2 f3 = u2f(acc[o2][3][pr]);
            const int b0 = bg * 4 + pr * 2;
            float4 r0 = make_float4(f0.x + bz.x, f1.x + bz.y, f2.x + bz.z, f3.x + bz.w);
            float4 r1 = make_float4(f0.y + bz.x, f1.y + bz.y, f2.y + bz.z, f3.y + bz.w);
            *reinterpret_cast<float4*>(out + ((size_t)(b0 * COUT + o)) * S_LEN + sbase) = r0;
            *reinterpret_cast<float4*>(out + ((size_t)((b0 + 1) * COUT + o)) * S_LEN + sbase) = r1;
        }
    }
}

extern "C" void kernel_launch(void* const* d_in, const int* in_sizes, int n_in,
                              void* d_out, int out_size) {
    const float* input  = (const float*)d_in[0];
    const float* weight = (const float*)d_in[1];
    const float* bias   = (const float*)d_in[2];
    float* out = (float*)d_out;

    cudaFuncSetAttribute(locon1d_kernel,
                         cudaFuncAttributeMaxDynamicSharedMemorySize, SMEM_BYTES);

    // 1) pull weight (50.3MB) into L2 at max streaming bandwidth
    const int n4 = (COUT * CIN * S_LEN * KW) / 4;   // 3,145,728 float4
    prefetch_kernel<<<2048, 256>>>((const float4*)weight, n4);

    // 2) conv, weights served from L2
    dim3 grid(S_LEN / S_TILE, COUT / O_TILE);   // (64, 4)
    locon1d_kernel<<<grid, THREADS, SMEM_BYTES>>>(input, weight, bias, out);
}